// round 15
// baseline (speedup 1.0000x reference)
#include <cuda_runtime.h>
#include <cuda_fp16.h>
#include <cstdint>

#define BB 4096
#define DD 2048
#define BD (BB * DD)

// ---------------- device scratch ----------------
// A: [phase(2)][4096][2048] fp16 row-major (x, h_prev)
__device__ __half g_Ahi[2ull * BB * DD];
// B: [gate*2+phase(8)][N=2048][K=2048] fp16 row-major (transposed W/U)
__device__ __half g_Bhi[8ull * DD * DD];

__device__ __forceinline__ uint32_t smem_u32(const void* p) {
    uint32_t a;
    asm("{ .reg .u64 t; cvta.to.shared.u64 t, %1; cvt.u32.u64 %0, t; }" : "=r"(a) : "l"(p));
    return a;
}
__device__ __forceinline__ unsigned long long pk4h(float a, float b, float c, float d) {
    __half2 lo = __floats2half2_rn(a, b);
    __half2 hi = __floats2half2_rn(c, d);
    return (unsigned long long)(*(uint32_t*)&lo) | ((unsigned long long)(*(uint32_t*)&hi) << 32);
}

// ---------------- Pack A: x / h_prev -> fp16 ---------------------------------
__global__ __launch_bounds__(256) void pack_a_kernel(
    const float* __restrict__ x, const float* __restrict__ h)
{
    uint32_t i = blockIdx.x * 256u + threadIdx.x;
    uint32_t k4 = i & 511u;
    uint32_t rest = i >> 9;
    uint32_t mm = rest & 4095u;
    uint32_t p = rest >> 12;
    const float* src = p ? h : x;
    uint32_t k = k4 * 4;
    float4 v = *(const float4*)&src[(size_t)mm * DD + k];

    size_t o = ((size_t)p * BB + mm) * DD + k;
    *(unsigned long long*)&g_Ahi[o] = pk4h(v.x, v.y, v.z, v.w);
}

// ---------------- Pack B: transpose W/U -> [N][K] fp16 ----------------------
__global__ __launch_bounds__(256) void pack_b_kernel(
    const float* __restrict__ W0, const float* __restrict__ W1,
    const float* __restrict__ W2, const float* __restrict__ W3,
    const float* __restrict__ W4, const float* __restrict__ W5,
    const float* __restrict__ W6, const float* __restrict__ W7)
{
    __shared__ float s[64][65];
    const float* mats[8] = {W0, W1, W2, W3, W4, W5, W6, W7};
    const int gp = blockIdx.z;            // gate*2 + phase
    const float* src = mats[gp];
    const int kb = blockIdx.x, nb = blockIdx.y;
    const int t = threadIdx.x;

    const int cn = (t & 15) * 4;
    const int r0 = t >> 4;
    #pragma unroll
    for (int pass = 0; pass < 4; ++pass) {
        int r = pass * 16 + r0;
        float4 v = *(const float4*)&src[(size_t)(kb * 64 + r) * DD + nb * 64 + cn];
        s[r][cn] = v.x; s[r][cn + 1] = v.y; s[r][cn + 2] = v.z; s[r][cn + 3] = v.w;
    }
    __syncthreads();

    const int orow = t >> 2;
    const int kbase = (t & 3) * 16;
    size_t base = (size_t)gp * DD * DD + (size_t)(nb * 64 + orow) * DD + kb * 64;
    #pragma unroll
    for (int u = 0; u < 4; ++u) {
        int kl = kbase + u * 4;
        float v0 = s[kl][orow], v1 = s[kl + 1][orow];
        float v2 = s[kl + 2][orow], v3 = s[kl + 3][orow];
        *(unsigned long long*)&g_Bhi[base + kl] = pk4h(v0, v1, v2, v3);
    }
}

// ---------------- 4-gate fused fp16 GEMM (f32 acc) + in-CTA sLSTM epilogue --
// CTA tile: 64(M) x 128(N) x 4 gates. 16 warps = (gate 4, mw 2, nw 2),
// warp tile 32x64 per gate. A tile shared across gates (4x reuse).
// Stage = A 8KB + 4xB 16KB = 72KB; 3 stages = 216KB, 1 CTA/SM, 16 warps.
// After mainloop: accum -> smem (f32, padded) -> full cell update in-kernel.
#define BM 64
#define BN 128
#define BKT 64
#define NITERS 64             // 2 phases * 32 k-steps
#define A_OFF 0
#define B_OFF 8192
#define STAGE_BYTES 73728
#define SMEM_TOTAL (3 * STAGE_BYTES)
#define EPI_STRIDE 132        // padded f32 row stride (bank-conflict-free)

__device__ __forceinline__ uint32_t sw_off(uint32_t row, uint32_t chunk) {
    return row * 128u + ((chunk ^ (row & 7u)) << 4);
}
__device__ __forceinline__ void cp16(uint32_t saddr, const void* gaddr) {
    asm volatile("cp.async.cg.shared.global [%0], [%1], 16;" :: "r"(saddr), "l"(gaddr));
}

__device__ __forceinline__ void gemm_issue(
    int t, int stage, uint32_t sb, int m0, int n0, int tid)
{
    const int phase = t >> 5;
    const int k0 = (t & 31) * BKT;

    const uint32_t st = sb + stage * STAGE_BYTES;

    // A: 64 rows x 8 chunks -> 512 cp16, one per thread
    {
        const uint32_t arow = tid >> 3;
        const uint32_t ach  = tid & 7;
        const __half* Ag = g_Ahi + (size_t)phase * BB * DD + (size_t)(m0 + arow) * DD + k0;
        cp16(st + A_OFF + sw_off(arow, ach), Ag + ach * 8);
    }
    // B: 4 gates x 128 rows x 8 chunks -> 4096 cp16, eight per thread
    {
        const uint32_t bg   = tid >> 7;          // gate 0..3
        const uint32_t brow = tid & 127;
        const __half* Bg = g_Bhi + (size_t)(bg * 2 + phase) * DD * DD
                         + (size_t)(n0 + brow) * DD + k0;
        const uint32_t bbase = st + B_OFF + bg * 16384u;
        #pragma unroll
        for (int ch = 0; ch < 8; ++ch)
            cp16(bbase + sw_off(brow, ch), Bg + ch * 8);
    }
}

__global__ __launch_bounds__(512, 1) void slstm_gemm(
    const float* __restrict__ cprev, const float* __restrict__ nprev,
    const float* __restrict__ bI, const float* __restrict__ bF,
    const float* __restrict__ bO, const float* __restrict__ bZ,
    float* __restrict__ out)
{
    extern __shared__ char smem[];
    const uint32_t sb = smem_u32(smem);
    const int tid = threadIdx.x;
    const int lane = tid & 31;
    const int wid = tid >> 5;
    const int m0 = blockIdx.x * BM;       // mtile fast -> ntile groups share B
    const int n0 = blockIdx.y * BN;
    const int g  = wid & 3;               // gate
    const int wm = ((wid >> 2) & 1) * 32; // warp M origin (0/32)
    const int wn = (wid >> 3) * 64;       // warp N origin (0/64)

    float d[2][8][4];                     // 32x64 warp tile accum (f32)
    #pragma unroll
    for (int mi = 0; mi < 2; ++mi)
        #pragma unroll
        for (int nj = 0; nj < 8; ++nj)
            #pragma unroll
            for (int e = 0; e < 4; ++e) d[mi][nj][e] = 0.0f;

    gemm_issue(0, 0, sb, m0, n0, tid);
    asm volatile("cp.async.commit_group;" ::: "memory");
    gemm_issue(1, 1, sb, m0, n0, tid);
    asm volatile("cp.async.commit_group;" ::: "memory");

    #pragma unroll 1
    for (int t = 0; t < NITERS; ++t) {
        asm volatile("cp.async.wait_group 1;" ::: "memory");
        __syncthreads();

        if (t + 2 < NITERS)
            gemm_issue(t + 2, (t + 2) % 3, sb, m0, n0, tid);
        asm volatile("cp.async.commit_group;" ::: "memory");

        const int stage = t % 3;
        const uint32_t st = sb + stage * STAGE_BYTES;
        const uint32_t bB = st + B_OFF + g * 16384u;

        #pragma unroll
        for (int ks = 0; ks < 4; ++ks) {
            uint32_t a[2][4];
            #pragma unroll
            for (int mi = 0; mi < 2; ++mi) {
                uint32_t row = wm + mi * 16 + (lane & 15);
                uint32_t ch  = ks * 2 + (lane >> 4);
                asm volatile("ldmatrix.sync.aligned.m8n8.x4.shared.b16 {%0,%1,%2,%3}, [%4];"
                             : "=r"(a[mi][0]), "=r"(a[mi][1]), "=r"(a[mi][2]), "=r"(a[mi][3])
                             : "r"(st + A_OFF + sw_off(row, ch)));
            }
            uint32_t b[4][4];
            #pragma unroll
            for (int q = 0; q < 4; ++q) {
                uint32_t row = wn + q * 16 + (lane & 7) + ((lane >> 4) << 3);
                uint32_t ch  = ks * 2 + ((lane >> 3) & 1);
                asm volatile("ldmatrix.sync.aligned.m8n8.x4.shared.b16 {%0,%1,%2,%3}, [%4];"
                             : "=r"(b[q][0]), "=r"(b[q][1]), "=r"(b[q][2]), "=r"(b[q][3])
                             : "r"(bB + sw_off(row, ch)));
            }
            #pragma unroll
            for (int mi = 0; mi < 2; ++mi) {
                #pragma unroll
                for (int nj = 0; nj < 8; ++nj) {
                    uint32_t b0 = b[nj >> 1][(nj & 1) * 2];
                    uint32_t b1 = b[nj >> 1][(nj & 1) * 2 + 1];
                    asm volatile(
                        "mma.sync.aligned.m16n8k16.row.col.f32.f16.f16.f32 "
                        "{%0,%1,%2,%3}, {%4,%5,%6,%7}, {%8,%9}, {%0,%1,%2,%3};"
                        : "+f"(d[mi][nj][0]), "+f"(d[mi][nj][1]),
                          "+f"(d[mi][nj][2]), "+f"(d[mi][nj][3])
                        : "r"(a[mi][0]), "r"(a[mi][1]), "r"(a[mi][2]), "r"(a[mi][3]),
                          "r"(b0), "r"(b1));
                }
            }
        }
    }

    // ---- stage all 4 gates' accumulators through smem (f32, padded) ----
    __syncthreads();                       // all MMA reads of stages done
    float* sacc = (float*)smem;            // [4][64][EPI_STRIDE]
    #pragma unroll
    for (int mi = 0; mi < 2; ++mi) {
        #pragma unroll
        for (int nj = 0; nj < 8; ++nj) {
            int r = wm + mi * 16 + (lane >> 2);
            int c = wn + nj * 8 + (lane & 3) * 2;
            float* p0 = &sacc[(size_t)(g * 64 + r) * EPI_STRIDE + c];
            float* p1 = &sacc[(size_t)(g * 64 + r + 8) * EPI_STRIDE + c];
            p0[0] = d[mi][nj][0]; p0[1] = d[mi][nj][1];
            p1[0] = d[mi][nj][2]; p1[1] = d[mi][nj][3];
        }
    }
    __syncthreads();

    // ---- in-CTA sLSTM cell update for the 64x128 tile ----
    const int col = (tid & 31) * 4;        // 0..124
    const int rowbase = tid >> 5;          // 0..15
    const int j = n0 + col;
    float4 bi4 = *(const float4*)&bI[j];
    float4 bf4 = *(const float4*)&bF[j];
    float4 bo4 = *(const float4*)&bO[j];
    float4 bz4 = *(const float4*)&bZ[j];

    #pragma unroll
    for (int u = 0; u < 4; ++u) {
        int row = rowbase + u * 16;        // 0..63
        size_t idx = (size_t)(m0 + row) * DD + j;

        float4 pi4 = *(const float4*)&sacc[(size_t)(0 * 64 + row) * EPI_STRIDE + col];
        float4 pf4 = *(const float4*)&sacc[(size_t)(1 * 64 + row) * EPI_STRIDE + col];
        float4 po4 = *(const float4*)&sacc[(size_t)(2 * 64 + row) * EPI_STRIDE + col];
        float4 pz4 = *(const float4*)&sacc[(size_t)(3 * 64 + row) * EPI_STRIDE + col];
        float4 cp4 = *(const float4*)&cprev[idx];
        float4 np4 = *(const float4*)&nprev[idx];

        float pi[4] = {pi4.x + bi4.x, pi4.y + bi4.y, pi4.z + bi4.z, pi4.w + bi4.w};
        float pf[4] = {pf4.x + bf4.x, pf4.y + bf4.y, pf4.z + bf4.z, pf4.w + bf4.w};
        float po[4] = {po4.x + bo4.x, po4.y + bo4.y, po4.z + bo4.z, po4.w + bo4.w};
        float pz[4] = {pz4.x + bz4.x, pz4.y + bz4.y, pz4.z + bz4.z, pz4.w + bz4.w};
        float cp[4] = {cp4.x, cp4.y, cp4.z, cp4.w};
        float np[4] = {np4.x, np4.y, np4.z, np4.w};

        float hv[4], cv[4], nv[4];
        #pragma unroll
        for (int e = 0; e < 4; ++e) {
            float ig = __expf(pi[e]);
            float fg = __expf(pf[e]);
            float og = 1.0f / (1.0f + __expf(-po[e]));
            float zg = tanhf(pz[e]);
            float cc = fg * cp[e] + ig * zg;
            float nn = fg * np[e] + ig;
            cv[e] = cc; nv[e] = nn;
            hv[e] = og * (cc / (nn + 1e-6f));
        }
        *(float4*)&out[idx]                   = *(float4*)hv;
        *(float4*)&out[(size_t)BD + idx]      = *(float4*)cv;
        *(float4*)&out[2 * (size_t)BD + idx]  = *(float4*)nv;
    }
}

// ---------------- launch -----------------------------------------------------
extern "C" void kernel_launch(void* const* d_in, const int* in_sizes, int n_in,
                              void* d_out, int out_size)
{
    const float* x     = (const float*)d_in[0];
    const float* hprev = (const float*)d_in[1];
    const float* cprev = (const float*)d_in[2];
    const float* nprev = (const float*)d_in[3];
    const float* Wi = (const float*)d_in[4];
    const float* bi = (const float*)d_in[5];
    const float* Ui = (const float*)d_in[6];
    const float* Wf = (const float*)d_in[7];
    const float* bf_ = (const float*)d_in[8];
    const float* Uf = (const float*)d_in[9];
    const float* Wo = (const float*)d_in[10];
    const float* bo = (const float*)d_in[11];
    const float* Uo = (const float*)d_in[12];
    const float* Wz = (const float*)d_in[13];
    const float* bz = (const float*)d_in[14];
    const float* Uz = (const float*)d_in[15];
    float* out = (float*)d_out;

    cudaFuncSetAttribute(slstm_gemm,
                         cudaFuncAttributeMaxDynamicSharedMemorySize, SMEM_TOTAL);

    pack_a_kernel<<<16384, 256>>>(x, hprev);
    pack_b_kernel<<<dim3(32, 32, 8), 256>>>(Wi, Ui, Wf, Uf, Wo, Uo, Wz, Uz);
    slstm_gemm<<<dim3(BB / BM, DD / BN), 512, SMEM_TOTAL>>>(
        cprev, nprev, bi, bf_, bo, bz, out);
}

// round 16
// speedup vs baseline: 1.5790x; 1.5790x over previous
#include <cuda_runtime.h>
#include <cuda_fp16.h>
#include <cstdint>

#define BB 4096
#define DD 2048
#define BD (BB * DD)

// ---------------- device scratch ----------------
// A: [phase(2)][4096][2048] fp16 row-major (x, h_prev)
__device__ __half g_Ahi[2ull * BB * DD];
// B: [gate*2+phase(8)][N=2048][K=2048] fp16 row-major (transposed W/U)
__device__ __half g_Bhi[8ull * DD * DD];
// Pre-activations: [gate(4)][4096][2048] fp16 (halved traffic; mostly L2-hit
// when the epilogue launches right behind the GEMM)
__device__ __half g_P[4ull * BD];

__device__ __forceinline__ uint32_t smem_u32(const void* p) {
    uint32_t a;
    asm("{ .reg .u64 t; cvta.to.shared.u64 t, %1; cvt.u32.u64 %0, t; }" : "=r"(a) : "l"(p));
    return a;
}
__device__ __forceinline__ unsigned long long pk4h(float a, float b, float c, float d) {
    __half2 lo = __floats2half2_rn(a, b);
    __half2 hi = __floats2half2_rn(c, d);
    return (unsigned long long)(*(uint32_t*)&lo) | ((unsigned long long)(*(uint32_t*)&hi) << 32);
}

// ---------------- Pack A: x / h_prev -> fp16 ---------------------------------
__global__ __launch_bounds__(256) void pack_a_kernel(
    const float* __restrict__ x, const float* __restrict__ h)
{
    uint32_t i = blockIdx.x * 256u + threadIdx.x;
    uint32_t k4 = i & 511u;
    uint32_t rest = i >> 9;
    uint32_t mm = rest & 4095u;
    uint32_t p = rest >> 12;
    const float* src = p ? h : x;
    uint32_t k = k4 * 4;
    float4 v = *(const float4*)&src[(size_t)mm * DD + k];

    size_t o = ((size_t)p * BB + mm) * DD + k;
    *(unsigned long long*)&g_Ahi[o] = pk4h(v.x, v.y, v.z, v.w);
}

// ---------------- Pack B: transpose W/U -> [N][K] fp16 ----------------------
__global__ __launch_bounds__(256) void pack_b_kernel(
    const float* __restrict__ W0, const float* __restrict__ W1,
    const float* __restrict__ W2, const float* __restrict__ W3,
    const float* __restrict__ W4, const float* __restrict__ W5,
    const float* __restrict__ W6, const float* __restrict__ W7)
{
    __shared__ float s[64][65];
    const float* mats[8] = {W0, W1, W2, W3, W4, W5, W6, W7};
    const int gp = blockIdx.z;            // gate*2 + phase
    const float* src = mats[gp];
    const int kb = blockIdx.x, nb = blockIdx.y;
    const int t = threadIdx.x;

    const int cn = (t & 15) * 4;
    const int r0 = t >> 4;
    #pragma unroll
    for (int pass = 0; pass < 4; ++pass) {
        int r = pass * 16 + r0;
        float4 v = *(const float4*)&src[(size_t)(kb * 64 + r) * DD + nb * 64 + cn];
        s[r][cn] = v.x; s[r][cn + 1] = v.y; s[r][cn + 2] = v.z; s[r][cn + 3] = v.w;
    }
    __syncthreads();

    const int orow = t >> 2;
    const int kbase = (t & 3) * 16;
    size_t base = (size_t)gp * DD * DD + (size_t)(nb * 64 + orow) * DD + kb * 64;
    #pragma unroll
    for (int u = 0; u < 4; ++u) {
        int kl = kbase + u * 4;
        float v0 = s[kl][orow], v1 = s[kl + 1][orow];
        float v2 = s[kl + 2][orow], v3 = s[kl + 3][orow];
        *(unsigned long long*)&g_Bhi[base + kl] = pk4h(v0, v1, v2, v3);
    }
}

// ---------------- fp16 GEMM, f32 accumulate (R12 structure, proven) ---------
// BM=128, BN=128, BK=64; 512 threads, 16 warps, warp tile 32x32; 2 CTAs/SM.
#define BM 128
#define BN 128
#define BKT 64
#define NITERS 64             // 2 phases * 32 k-steps
#define A_OFF 0
#define B_OFF 16384
#define STAGE_BYTES 32768
#define SMEM_TOTAL (3 * STAGE_BYTES)

__device__ __forceinline__ uint32_t sw_off(uint32_t row, uint32_t chunk) {
    return row * 128u + ((chunk ^ (row & 7u)) << 4);
}
__device__ __forceinline__ void cp16(uint32_t saddr, const void* gaddr) {
    asm volatile("cp.async.cg.shared.global [%0], [%1], 16;" :: "r"(saddr), "l"(gaddr));
}

__device__ __forceinline__ void gemm_issue(
    int g, int t, int stage, uint32_t sb, int m0, int n0, int tid)
{
    const int phase = t >> 5;
    const int k0 = (t & 31) * BKT;

    const __half* Ap = g_Ahi + (size_t)phase * BB * DD;
    const __half* Bp = g_Bhi + (size_t)(g * 2 + phase) * DD * DD;

    const uint32_t st = sb + stage * STAGE_BYTES;

    const uint32_t row = tid >> 2;           // 0..127
    const uint32_t cb  = (tid & 3) * 2;      // chunk base 0,2,4,6
    const __half* Ag = Ap + (size_t)(m0 + row) * DD + k0;
    const __half* Bg = Bp + (size_t)(n0 + row) * DD + k0;
    cp16(st + A_OFF + sw_off(row, cb),     Ag + cb * 8);
    cp16(st + A_OFF + sw_off(row, cb + 1), Ag + cb * 8 + 8);
    cp16(st + B_OFF + sw_off(row, cb),     Bg + cb * 8);
    cp16(st + B_OFF + sw_off(row, cb + 1), Bg + cb * 8 + 8);
}

__global__ __launch_bounds__(512, 1) void slstm_gemm(__half* __restrict__ P)
{
    extern __shared__ char smem[];
    const uint32_t sb = smem_u32(smem);
    const int tid = threadIdx.x;
    const int lane = tid & 31;
    const int wid = tid >> 5;
    const int m0 = blockIdx.x * BM;
    const int n0 = blockIdx.y * BN;
    const int g  = blockIdx.z;
    const int wm = (wid & 3) * 32;        // warp M origin
    const int wn = (wid >> 2) * 32;       // warp N origin

    float d[2][4][4];                     // accum (f32)
    #pragma unroll
    for (int mi = 0; mi < 2; ++mi)
        #pragma unroll
        for (int nj = 0; nj < 4; ++nj)
            #pragma unroll
            for (int e = 0; e < 4; ++e) d[mi][nj][e] = 0.0f;

    gemm_issue(g, 0, 0, sb, m0, n0, tid);
    asm volatile("cp.async.commit_group;" ::: "memory");
    gemm_issue(g, 1, 1, sb, m0, n0, tid);
    asm volatile("cp.async.commit_group;" ::: "memory");

    #pragma unroll 1
    for (int t = 0; t < NITERS; ++t) {
        asm volatile("cp.async.wait_group 1;" ::: "memory");
        __syncthreads();

        if (t + 2 < NITERS)
            gemm_issue(g, t + 2, (t + 2) % 3, sb, m0, n0, tid);
        asm volatile("cp.async.commit_group;" ::: "memory");

        const int stage = t % 3;
        const uint32_t st = sb + stage * STAGE_BYTES;

        #pragma unroll
        for (int ks = 0; ks < 4; ++ks) {
            uint32_t a[2][4];
            #pragma unroll
            for (int mi = 0; mi < 2; ++mi) {
                uint32_t row = wm + mi * 16 + (lane & 15);
                uint32_t ch  = ks * 2 + (lane >> 4);
                asm volatile("ldmatrix.sync.aligned.m8n8.x4.shared.b16 {%0,%1,%2,%3}, [%4];"
                             : "=r"(a[mi][0]), "=r"(a[mi][1]), "=r"(a[mi][2]), "=r"(a[mi][3])
                             : "r"(st + A_OFF + sw_off(row, ch)));
            }
            uint32_t b[2][4];
            #pragma unroll
            for (int q = 0; q < 2; ++q) {
                uint32_t row = wn + q * 16 + (lane & 7) + ((lane >> 4) << 3);
                uint32_t ch  = ks * 2 + ((lane >> 3) & 1);
                asm volatile("ldmatrix.sync.aligned.m8n8.x4.shared.b16 {%0,%1,%2,%3}, [%4];"
                             : "=r"(b[q][0]), "=r"(b[q][1]), "=r"(b[q][2]), "=r"(b[q][3])
                             : "r"(st + B_OFF + sw_off(row, ch)));
            }
            #pragma unroll
            for (int mi = 0; mi < 2; ++mi) {
                #pragma unroll
                for (int nj = 0; nj < 4; ++nj) {
                    uint32_t b0 = b[nj >> 1][(nj & 1) * 2];
                    uint32_t b1 = b[nj >> 1][(nj & 1) * 2 + 1];
                    asm volatile(
                        "mma.sync.aligned.m16n8k16.row.col.f32.f16.f16.f32 "
                        "{%0,%1,%2,%3}, {%4,%5,%6,%7}, {%8,%9}, {%0,%1,%2,%3};"
                        : "+f"(d[mi][nj][0]), "+f"(d[mi][nj][1]),
                          "+f"(d[mi][nj][2]), "+f"(d[mi][nj][3])
                        : "r"(a[mi][0]), "r"(a[mi][1]), "r"(a[mi][2]), "r"(a[mi][3]),
                          "r"(b0), "r"(b1));
                }
            }
        }
    }

    // write pre-activations (fp16: half the traffic, L2-resident for the epi)
    __half* Pg = P + (size_t)g * BD;
    #pragma unroll
    for (int mi = 0; mi < 2; ++mi) {
        #pragma unroll
        for (int nj = 0; nj < 4; ++nj) {
            int r = m0 + wm + mi * 16 + (lane >> 2);
            int c = n0 + wn + nj * 8 + (lane & 3) * 2;
            __half2 h0 = __floats2half2_rn(d[mi][nj][0], d[mi][nj][1]);
            __half2 h1 = __floats2half2_rn(d[mi][nj][2], d[mi][nj][3]);
            *(uint32_t*)&Pg[(size_t)r * DD + c]       = *(uint32_t*)&h0;
            *(uint32_t*)&Pg[(size_t)(r + 8) * DD + c] = *(uint32_t*)&h1;
        }
    }
}

// ---------------- fused sLSTM epilogue (bandwidth-bound) --------------------
__global__ __launch_bounds__(256) void slstm_epi(
    const float* __restrict__ cprev, const float* __restrict__ nprev,
    const float* __restrict__ bI, const float* __restrict__ bF,
    const float* __restrict__ bO, const float* __restrict__ bZ,
    float* __restrict__ out)
{
    size_t i = ((size_t)blockIdx.x * 256 + threadIdx.x) * 4;
    int j = (int)(i & 2047u);

    uint2 pi2 = *(const uint2*)&g_P[i];
    uint2 pf2 = *(const uint2*)&g_P[(size_t)BD + i];
    uint2 po2 = *(const uint2*)&g_P[2 * (size_t)BD + i];
    uint2 pz2 = *(const uint2*)&g_P[3 * (size_t)BD + i];
    float4 bi4 = *(const float4*)&bI[j];
    float4 bf4 = *(const float4*)&bF[j];
    float4 bo4 = *(const float4*)&bO[j];
    float4 bz4 = *(const float4*)&bZ[j];
    float4 cp4 = *(const float4*)&cprev[i];
    float4 np4 = *(const float4*)&nprev[i];

    float2 pia = __half22float2(*(__half2*)&pi2.x);
    float2 pib = __half22float2(*(__half2*)&pi2.y);
    float2 pfa = __half22float2(*(__half2*)&pf2.x);
    float2 pfb = __half22float2(*(__half2*)&pf2.y);
    float2 poa = __half22float2(*(__half2*)&po2.x);
    float2 pob = __half22float2(*(__half2*)&po2.y);
    float2 pza = __half22float2(*(__half2*)&pz2.x);
    float2 pzb = __half22float2(*(__half2*)&pz2.y);

    float pi[4] = {pia.x + bi4.x, pia.y + bi4.y, pib.x + bi4.z, pib.y + bi4.w};
    float pf[4] = {pfa.x + bf4.x, pfa.y + bf4.y, pfb.x + bf4.z, pfb.y + bf4.w};
    float po[4] = {poa.x + bo4.x, poa.y + bo4.y, pob.x + bo4.z, pob.y + bo4.w};
    float pz[4] = {pza.x + bz4.x, pza.y + bz4.y, pzb.x + bz4.z, pzb.y + bz4.w};
    float cp[4] = {cp4.x, cp4.y, cp4.z, cp4.w};
    float np[4] = {np4.x, np4.y, np4.z, np4.w};

    float hv[4], cv[4], nv[4];
    #pragma unroll
    for (int e = 0; e < 4; ++e) {
        float ig = __expf(pi[e]);
        float fg = __expf(pf[e]);
        float og = 1.0f / (1.0f + __expf(-po[e]));
        float zg = tanhf(pz[e]);
        float cc = fg * cp[e] + ig * zg;
        float nn = fg * np[e] + ig;
        cv[e] = cc; nv[e] = nn;
        hv[e] = og * (cc / (nn + 1e-6f));
    }
    *(float4*)&out[i]                   = *(float4*)hv;
    *(float4*)&out[(size_t)BD + i]      = *(float4*)cv;
    *(float4*)&out[2 * (size_t)BD + i]  = *(float4*)nv;
}

// ---------------- launch -----------------------------------------------------
extern "C" void kernel_launch(void* const* d_in, const int* in_sizes, int n_in,
                              void* d_out, int out_size)
{
    const float* x     = (const float*)d_in[0];
    const float* hprev = (const float*)d_in[1];
    const float* cprev = (const float*)d_in[2];
    const float* nprev = (const float*)d_in[3];
    const float* Wi = (const float*)d_in[4];
    const float* bi = (const float*)d_in[5];
    const float* Ui = (const float*)d_in[6];
    const float* Wf = (const float*)d_in[7];
    const float* bf_ = (const float*)d_in[8];
    const float* Uf = (const float*)d_in[9];
    const float* Wo = (const float*)d_in[10];
    const float* bo = (const float*)d_in[11];
    const float* Uo = (const float*)d_in[12];
    const float* Wz = (const float*)d_in[13];
    const float* bz = (const float*)d_in[14];
    const float* Uz = (const float*)d_in[15];
    float* out = (float*)d_out;

    cudaFuncSetAttribute(slstm_gemm,
                         cudaFuncAttributeMaxDynamicSharedMemorySize, SMEM_TOTAL);

    __half* Pptr = nullptr;
    cudaGetSymbolAddress((void**)&Pptr, g_P);

    pack_a_kernel<<<16384, 256>>>(x, hprev);
    pack_b_kernel<<<dim3(32, 32, 8), 256>>>(Wi, Ui, Wf, Uf, Wo, Uo, Wz, Uz);
    slstm_gemm<<<dim3(BB / BM, DD / BN, 4), 512, SMEM_TOTAL>>>(Pptr);
    slstm_epi<<<BD / 4 / 256, 256>>>(cprev, nprev, bi, bf_, bo, bz, out);
}